// round 1
// baseline (speedup 1.0000x reference)
#include <cuda_runtime.h>

// Double-precision global accumulator (scratch via __device__ global, per rules).
__device__ double g_accum;

__global__ void zero_accum_kernel() {
    g_accum = 0.0;
}

// Grid-stride vectorized dot-product reduction:
// acc += probs[i] * centroids[i] over all N*K elements.
__global__ void __launch_bounds__(512)
dot_reduce_kernel(const float4* __restrict__ p4,
                  const float4* __restrict__ c4,
                  long long n4,
                  const float* __restrict__ p_tail,
                  const float* __restrict__ c_tail,
                  int n_tail) {
    float acc = 0.0f;

    long long idx    = (long long)blockIdx.x * blockDim.x + threadIdx.x;
    long long stride = (long long)gridDim.x * blockDim.x;

    for (long long i = idx; i < n4; i += stride) {
        float4 a = p4[i];
        float4 b = c4[i];
        acc = fmaf(a.x, b.x, acc);
        acc = fmaf(a.y, b.y, acc);
        acc = fmaf(a.z, b.z, acc);
        acc = fmaf(a.w, b.w, acc);
    }

    // Scalar tail (handled by the first few threads of the grid).
    if (idx < n_tail) {
        acc = fmaf(p_tail[idx], c_tail[idx], acc);
    }

    // Warp reduction.
    #pragma unroll
    for (int off = 16; off > 0; off >>= 1)
        acc += __shfl_xor_sync(0xFFFFFFFFu, acc, off);

    // Block reduction via shared memory.
    __shared__ float warp_sums[16];  // 512 threads -> 16 warps
    int lane = threadIdx.x & 31;
    int wid  = threadIdx.x >> 5;
    if (lane == 0) warp_sums[wid] = acc;
    __syncthreads();

    if (wid == 0) {
        int nwarps = blockDim.x >> 5;
        float v = (lane < nwarps) ? warp_sums[lane] : 0.0f;
        #pragma unroll
        for (int off = 16; off > 0; off >>= 1)
            v += __shfl_xor_sync(0xFFFFFFFFu, v, off);
        if (lane == 0)
            atomicAdd(&g_accum, (double)v);
    }
}

__global__ void finalize_kernel(float* __restrict__ out, double inv_rows) {
    out[0] = (float)(g_accum * inv_rows);
}

extern "C" void kernel_launch(void* const* d_in, const int* in_sizes, int n_in,
                              void* d_out, int out_size) {
    const float* probs     = (const float*)d_in[0];
    const float* centroids = (const float*)d_in[1];
    float* out = (float*)d_out;

    long long n = (long long)in_sizes[0];   // N*K total elements
    const int K = 101;
    long long rows = n / K;

    long long n4 = n >> 2;                  // float4 count
    long long tail_start = n4 << 2;
    int n_tail = (int)(n - tail_start);

    zero_accum_kernel<<<1, 1>>>();

    // 148 SMs; 8 blocks/SM of 512 threads gives ample memory-level parallelism.
    int blocks = 148 * 8;
    dot_reduce_kernel<<<blocks, 512>>>(
        (const float4*)probs, (const float4*)centroids, n4,
        probs + tail_start, centroids + tail_start, n_tail);

    finalize_kernel<<<1, 1>>>(out, 1.0 / (double)rows);
}